// round 14
// baseline (speedup 1.0000x reference)
#include <cuda_runtime.h>
#include <cstdint>

// out = y * (mean(x,-1) + mean(y,-1)),  [64, 36, 4096] fp32, rows = 2304.
//
// R14: non-persistent, TWO rows per CTA (grid=1152). All four TMAs
// (x0,y0,x1,y1) issue up front on separate mbarriers; row 0 computes while
// row 1 streams in (deep prefetch without the persistent-kernel lockstep).
// Halves per-CTA prologue/epilogue overhead vs R13. Block reduction costs
// ONE __syncthreads per row (warp partials -> smem, every thread sums 8).
// Stores stay __stcs (measured-optimal policy).

constexpr int L_LEN     = 4096;
constexpr int NTHREADS  = 256;
constexpr int NWARPS    = NTHREADS / 32;
constexpr int ITERS     = L_LEN / (NTHREADS * 4);   // 4 float4 per thread
constexpr int ROW_BYTES = L_LEN * 4;                // 16 KB
constexpr int DYN_SMEM  = 4 * ROW_BYTES;            // x0,y0,x1,y1 = 64 KB

__device__ __forceinline__ uint32_t smem_u32(const void* p) {
    return (uint32_t)__cvta_generic_to_shared(p);
}

__device__ __forceinline__ void mbar_init(uint32_t mbar, uint32_t count) {
    asm volatile("mbarrier.init.shared.b64 [%0], %1;" :: "r"(mbar), "r"(count) : "memory");
}

__device__ __forceinline__ void mbar_expect_tx(uint32_t mbar, uint32_t bytes) {
    asm volatile("mbarrier.arrive.expect_tx.shared.b64 _, [%0], %1;"
                 :: "r"(mbar), "r"(bytes) : "memory");
}

__device__ __forceinline__ void bulk_ld(uint32_t dst_smem, const void* src, uint32_t bytes,
                                        uint32_t mbar) {
    asm volatile(
        "cp.async.bulk.shared::cluster.global.mbarrier::complete_tx::bytes "
        "[%0], [%1], %2, [%3];"
        :: "r"(dst_smem), "l"(src), "r"(bytes), "r"(mbar) : "memory");
}

__device__ __forceinline__ void mbar_wait(uint32_t mbar, uint32_t parity) {
    uint32_t done;
    asm volatile(
        "{\n\t"
        ".reg .pred p;\n\t"
        "mbarrier.try_wait.parity.acquire.cta.shared::cta.b64 p, [%1], %2;\n\t"
        "selp.b32 %0, 1, 0, p;\n\t"
        "}"
        : "=r"(done) : "r"(mbar), "r"(parity) : "memory");
    if (!done) {
        asm volatile(
            "{\n\t"
            ".reg .pred P1;\n\t"
            "WAIT_LOOP_%=:\n\t"
            "mbarrier.try_wait.parity.acquire.cta.shared::cta.b64 P1, [%0], %1, 0x989680;\n\t"
            "@P1 bra.uni WAIT_DONE_%=;\n\t"
            "bra.uni WAIT_LOOP_%=;\n\t"
            "WAIT_DONE_%=:\n\t"
            "}"
            :: "r"(mbar), "r"(parity) : "memory");
    }
}

__global__ __launch_bounds__(NTHREADS)
void spo2_2row_kernel(const float* __restrict__ x,
                      const float* __restrict__ y,
                      float* __restrict__ out)
{
    extern __shared__ float sbuf[];   // [x0 4096][y0 4096][x1 4096][y1 4096]
    __shared__ alignas(8) unsigned long long mbar_storage[4];
    __shared__ float warpsum[2][NWARPS];

    const int tid = threadIdx.x;
    const int wid = tid >> 5;
    const size_t base0 = (size_t)(2 * blockIdx.x) * L_LEN;

    if (tid == 0) {
#pragma unroll
        for (int i = 0; i < 4; i++)
            mbar_init(smem_u32(&mbar_storage[i]), 1);
    }
    __syncthreads();

    // Fire all four TMAs up front: row1 streams while row0 computes.
    if (tid == 0) {
#pragma unroll
        for (int r = 0; r < 2; r++) {
            const size_t rb = base0 + (size_t)r * L_LEN;
            const uint32_t mbx = smem_u32(&mbar_storage[2 * r]);
            const uint32_t mby = smem_u32(&mbar_storage[2 * r + 1]);
            mbar_expect_tx(mbx, ROW_BYTES);
            bulk_ld(smem_u32(sbuf + (2 * r) * L_LEN),     x + rb, ROW_BYTES, mbx);
            mbar_expect_tx(mby, ROW_BYTES);
            bulk_ld(smem_u32(sbuf + (2 * r + 1) * L_LEN), y + rb, ROW_BYTES, mby);
        }
    }

#pragma unroll
    for (int r = 0; r < 2; r++) {
        const size_t rb = base0 + (size_t)r * L_LEN;
        const float* sx = sbuf + (2 * r) * L_LEN;
        const float* sy = sbuf + (2 * r + 1) * L_LEN;

        // x first (lands first), overlap tail of y's TMA.
        mbar_wait(smem_u32(&mbar_storage[2 * r]), 0);

        const float4* sx4 = reinterpret_cast<const float4*>(sx);
        float t = 0.0f;
#pragma unroll
        for (int i = 0; i < ITERS; i++) {
            float4 a = sx4[i * NTHREADS + tid];
            t += (a.x + a.y) + (a.z + a.w);
        }

        mbar_wait(smem_u32(&mbar_storage[2 * r + 1]), 0);

        const float4* sy4 = reinterpret_cast<const float4*>(sy);
        float4 yv[ITERS];
#pragma unroll
        for (int i = 0; i < ITERS; i++) {
            yv[i] = sy4[i * NTHREADS + tid];
            t += (yv[i].x + yv[i].y) + (yv[i].z + yv[i].w);
        }

        // One-barrier block reduction: warp partials to smem, then every
        // thread sums all NWARPS partials itself (smem broadcast reads).
#pragma unroll
        for (int o = 16; o > 0; o >>= 1)
            t += __shfl_xor_sync(0xffffffffu, t, o);
        if ((tid & 31) == 0)
            warpsum[r][wid] = t;
        __syncthreads();

        float s = 0.0f;
#pragma unroll
        for (int w = 0; w < NWARPS; w++)
            s += warpsum[r][w];
        const float sc = s * (1.0f / (float)L_LEN);

        // Streaming (evict-first) stores — measured-optimal policy.
        float4* orow = reinterpret_cast<float4*>(out + rb);
#pragma unroll
        for (int i = 0; i < ITERS; i++) {
            float4 v = yv[i];
            v.x *= sc; v.y *= sc; v.z *= sc; v.w *= sc;
            __stcs(&orow[i * NTHREADS + tid], v);
        }
    }
}

extern "C" void kernel_launch(void* const* d_in, const int* in_sizes, int n_in,
                              void* d_out, int out_size)
{
    const float* x = (const float*)d_in[0];
    const float* y = (const float*)d_in[1];
    float* out = (float*)d_out;

    const int rows = in_sizes[0] / L_LEN;   // 2304

    cudaFuncSetAttribute(spo2_2row_kernel,
                         cudaFuncAttributeMaxDynamicSharedMemorySize, DYN_SMEM);

    spo2_2row_kernel<<<rows / 2, NTHREADS, DYN_SMEM>>>(x, y, out);
}

// round 15
// speedup vs baseline: 1.0221x; 1.0221x over previous
#include <cuda_runtime.h>
#include <cstdint>

// out = y * (mean(x,-1) + mean(y,-1)),  [64, 36, 4096] fp32, rows = 2304.
//
// R15: one row per CTA (best structure), tuned for EIGHT resident CTAs/SM
// (64 warps, occ 100%): smem must fit 28.5 KB and regs 32.
//   y : full 16 KB TMA landing buffer (live until the scaled store).
//   x : streamed through a 2 x 4 KB double-buffered chunk pipeline
//       (4 chunks, reissue into a drained buffer after a barrier).
// Total smem ~24.3 KB -> 8 CTAs/SM; __launch_bounds__(256,8) pins regs<=32.
// Waits: x chunks reduce while y's TMA streams; stores stay __stcs
// (policy sweep complete: cs < plain < wt < evict_last).

constexpr int L_LEN     = 4096;
constexpr int NTHREADS  = 256;
constexpr int NWARPS    = NTHREADS / 32;
constexpr int ITERS     = L_LEN / (NTHREADS * 4);   // 4 float4/thread for y
constexpr int ROW_BYTES = L_LEN * 4;                // 16 KB
constexpr int XCHUNK    = 1024;                     // floats per x chunk (4 KB)
constexpr int XCHUNK_BYTES = XCHUNK * 4;
constexpr int NXCHUNKS  = L_LEN / XCHUNK;           // 4

__device__ __forceinline__ uint32_t smem_u32(const void* p) {
    return (uint32_t)__cvta_generic_to_shared(p);
}

__device__ __forceinline__ void mbar_init(uint32_t mbar, uint32_t count) {
    asm volatile("mbarrier.init.shared.b64 [%0], %1;" :: "r"(mbar), "r"(count) : "memory");
}

__device__ __forceinline__ void mbar_expect_tx(uint32_t mbar, uint32_t bytes) {
    asm volatile("mbarrier.arrive.expect_tx.shared.b64 _, [%0], %1;"
                 :: "r"(mbar), "r"(bytes) : "memory");
}

__device__ __forceinline__ void bulk_ld(uint32_t dst_smem, const void* src, uint32_t bytes,
                                        uint32_t mbar) {
    asm volatile(
        "cp.async.bulk.shared::cluster.global.mbarrier::complete_tx::bytes "
        "[%0], [%1], %2, [%3];"
        :: "r"(dst_smem), "l"(src), "r"(bytes), "r"(mbar) : "memory");
}

__device__ __forceinline__ void mbar_wait(uint32_t mbar, uint32_t parity) {
    uint32_t done;
    asm volatile(
        "{\n\t"
        ".reg .pred p;\n\t"
        "mbarrier.try_wait.parity.acquire.cta.shared::cta.b64 p, [%1], %2;\n\t"
        "selp.b32 %0, 1, 0, p;\n\t"
        "}"
        : "=r"(done) : "r"(mbar), "r"(parity) : "memory");
    if (!done) {
        asm volatile(
            "{\n\t"
            ".reg .pred P1;\n\t"
            "WAIT_LOOP_%=:\n\t"
            "mbarrier.try_wait.parity.acquire.cta.shared::cta.b64 P1, [%0], %1, 0x989680;\n\t"
            "@P1 bra.uni WAIT_DONE_%=;\n\t"
            "bra.uni WAIT_LOOP_%=;\n\t"
            "WAIT_DONE_%=:\n\t"
            "}"
            :: "r"(mbar), "r"(parity) : "memory");
    }
}

__global__ __launch_bounds__(NTHREADS, 8)
void spo2_8cta_kernel(const float* __restrict__ x,
                      const float* __restrict__ y,
                      float* __restrict__ out)
{
    __shared__ alignas(128) float sy[L_LEN];            // 16 KB
    __shared__ alignas(128) float sxb[2][XCHUNK];       // 2 x 4 KB
    __shared__ alignas(8) unsigned long long mbar_storage[3];  // x0, x1, y
    __shared__ float warpsum[NWARPS];

    const int tid = threadIdx.x;
    const int wid = tid >> 5;
    const size_t row_base = (size_t)blockIdx.x * L_LEN;

    const uint32_t mbx0 = smem_u32(&mbar_storage[0]);
    const uint32_t mbx1 = smem_u32(&mbar_storage[1]);
    const uint32_t mby  = smem_u32(&mbar_storage[2]);

    if (tid == 0) {
        mbar_init(mbx0, 1);
        mbar_init(mbx1, 1);
        mbar_init(mby, 1);
    }
    __syncthreads();

    // Fire y (full row) and the first two x chunks immediately.
    if (tid == 0) {
        mbar_expect_tx(mby, ROW_BYTES);
        bulk_ld(smem_u32(sy), y + row_base, ROW_BYTES, mby);
        mbar_expect_tx(mbx0, XCHUNK_BYTES);
        bulk_ld(smem_u32(sxb[0]), x + row_base, XCHUNK_BYTES, mbx0);
        mbar_expect_tx(mbx1, XCHUNK_BYTES);
        bulk_ld(smem_u32(sxb[1]), x + row_base + XCHUNK, XCHUNK_BYTES, mbx1);
    }

    // Stream x through the 2-buffer chunk pipeline. Chunk c lives in buffer
    // c&1 with phase c>>1 (each buffer is used twice).
    float t = 0.0f;
#pragma unroll
    for (int c = 0; c < NXCHUNKS; c++) {
        const int b = c & 1;
        const uint32_t mb = b ? mbx1 : mbx0;
        mbar_wait(mb, c >> 1);

        float4 a = reinterpret_cast<const float4*>(sxb[b])[tid];  // 1024 fl = 256 f4
        t += (a.x + a.y) + (a.z + a.w);

        if (c + 2 < NXCHUNKS) {
            __syncthreads();   // all reads of buffer b done -> safe to refill
            if (tid == 0) {
                mbar_expect_tx(mb, XCHUNK_BYTES);
                bulk_ld(smem_u32(sxb[b]), x + row_base + (size_t)(c + 2) * XCHUNK,
                        XCHUNK_BYTES, mb);
            }
        }
    }

    // y: reduce from smem, keep in registers for the scaled store.
    mbar_wait(mby, 0);

    const float4* sy4 = reinterpret_cast<const float4*>(sy);
    float4 yv[ITERS];
#pragma unroll
    for (int i = 0; i < ITERS; i++) {
        yv[i] = sy4[i * NTHREADS + tid];
        t += (yv[i].x + yv[i].y) + (yv[i].z + yv[i].w);
    }

    // One-barrier block reduction: warp partials -> smem, each thread sums 8.
#pragma unroll
    for (int o = 16; o > 0; o >>= 1)
        t += __shfl_xor_sync(0xffffffffu, t, o);
    if ((tid & 31) == 0)
        warpsum[wid] = t;
    __syncthreads();

    float s = 0.0f;
#pragma unroll
    for (int w = 0; w < NWARPS; w++)
        s += warpsum[w];
    const float sc = s * (1.0f / (float)L_LEN);

    // Streaming (evict-first) stores — measured-optimal policy.
    float4* orow = reinterpret_cast<float4*>(out + row_base);
#pragma unroll
    for (int i = 0; i < ITERS; i++) {
        float4 v = yv[i];
        v.x *= sc; v.y *= sc; v.z *= sc; v.w *= sc;
        __stcs(&orow[i * NTHREADS + tid], v);
    }
}

extern "C" void kernel_launch(void* const* d_in, const int* in_sizes, int n_in,
                              void* d_out, int out_size)
{
    const float* x = (const float*)d_in[0];
    const float* y = (const float*)d_in[1];
    float* out = (float*)d_out;

    const int rows = in_sizes[0] / L_LEN;   // 2304
    spo2_8cta_kernel<<<rows, NTHREADS>>>(x, y, out);
}

// round 16
// speedup vs baseline: 1.0830x; 1.0596x over previous
#include <cuda_runtime.h>
#include <cstdint>

// out = y * (mean(x,-1) + mean(y,-1)),  [64, 36, 4096] fp32, rows = 2304.
//
// R16 = R13-exact structure (one CTA/row, non-persistent, TMA loads on split
// mbarriers, x reduced while y streams, y register-held, __stcs stores) with
// ONE change: asymmetric L2 load policy.
//   x TMA -> evict_first  (x never claims L2 residency)
//   y TMA -> evict_last   (y's 37.7 MB becomes the resident set; fits L2)
// Goal: stop x and y competing for residency; warm replays then serve y
// reads from L2 and pay DRAM only for x reads + out writes (~75 MB/replay).

constexpr int L_LEN     = 4096;
constexpr int NTHREADS  = 256;
constexpr int NWARPS    = NTHREADS / 32;
constexpr int ITERS     = L_LEN / (NTHREADS * 4);   // 4 float4 per thread
constexpr int ROW_BYTES = L_LEN * 4;                // 16 KB

__device__ __forceinline__ uint32_t smem_u32(const void* p) {
    return (uint32_t)__cvta_generic_to_shared(p);
}

__device__ __forceinline__ void mbar_init(uint32_t mbar, uint32_t count) {
    asm volatile("mbarrier.init.shared.b64 [%0], %1;" :: "r"(mbar), "r"(count) : "memory");
}

__device__ __forceinline__ void mbar_expect_tx(uint32_t mbar, uint32_t bytes) {
    asm volatile("mbarrier.arrive.expect_tx.shared.b64 _, [%0], %1;"
                 :: "r"(mbar), "r"(bytes) : "memory");
}

__device__ __forceinline__ uint64_t pol_evict_first() {
    uint64_t pol;
    asm volatile("createpolicy.fractional.L2::evict_first.b64 %0, 1.0;" : "=l"(pol));
    return pol;
}

__device__ __forceinline__ uint64_t pol_evict_last() {
    uint64_t pol;
    asm volatile("createpolicy.fractional.L2::evict_last.b64 %0, 1.0;" : "=l"(pol));
    return pol;
}

__device__ __forceinline__ void bulk_ld_pol(uint32_t dst_smem, const void* src,
                                            uint32_t bytes, uint32_t mbar, uint64_t pol) {
    asm volatile(
        "cp.async.bulk.shared::cluster.global.mbarrier::complete_tx::bytes.L2::cache_hint "
        "[%0], [%1], %2, [%3], %4;"
        :: "r"(dst_smem), "l"(src), "r"(bytes), "r"(mbar), "l"(pol) : "memory");
}

__device__ __forceinline__ void mbar_wait(uint32_t mbar, uint32_t parity) {
    uint32_t done;
    asm volatile(
        "{\n\t"
        ".reg .pred p;\n\t"
        "mbarrier.try_wait.parity.acquire.cta.shared::cta.b64 p, [%1], %2;\n\t"
        "selp.b32 %0, 1, 0, p;\n\t"
        "}"
        : "=r"(done) : "r"(mbar), "r"(parity) : "memory");
    if (!done) {
        asm volatile(
            "{\n\t"
            ".reg .pred P1;\n\t"
            "WAIT_LOOP_%=:\n\t"
            "mbarrier.try_wait.parity.acquire.cta.shared::cta.b64 P1, [%0], %1, 0x989680;\n\t"
            "@P1 bra.uni WAIT_DONE_%=;\n\t"
            "bra.uni WAIT_LOOP_%=;\n\t"
            "WAIT_DONE_%=:\n\t"
            "}"
            :: "r"(mbar), "r"(parity) : "memory");
    }
}

__global__ __launch_bounds__(NTHREADS)
void spo2_asym_kernel(const float* __restrict__ x,
                      const float* __restrict__ y,
                      float* __restrict__ out)
{
    __shared__ alignas(128) float sx[L_LEN];
    __shared__ alignas(128) float sy[L_LEN];
    __shared__ alignas(8) unsigned long long mbar_storage[2];
    __shared__ float warpsum[NWARPS];

    const int tid = threadIdx.x;
    const int wid = tid >> 5;
    const uint32_t mbx = smem_u32(&mbar_storage[0]);
    const uint32_t mby = smem_u32(&mbar_storage[1]);
    const size_t row_base = (size_t)blockIdx.x * L_LEN;

    if (tid == 0) {
        mbar_init(mbx, 1);
        mbar_init(mby, 1);
    }
    __syncthreads();

    // Asymmetric residency: x evict_first (transient), y evict_last
    // (resident set). Both fired immediately on separate barriers.
    if (tid == 0) {
        mbar_expect_tx(mbx, ROW_BYTES);
        bulk_ld_pol(smem_u32(sx), x + row_base, ROW_BYTES, mbx, pol_evict_first());
        mbar_expect_tx(mby, ROW_BYTES);
        bulk_ld_pol(smem_u32(sy), y + row_base, ROW_BYTES, mby, pol_evict_last());
    }

    // x arrives -> reduce while y's TMA finishes.
    mbar_wait(mbx, 0);

    const float4* sx4 = reinterpret_cast<const float4*>(sx);
    float t = 0.0f;
#pragma unroll
    for (int i = 0; i < ITERS; i++) {
        float4 a = sx4[i * NTHREADS + tid];
        t += (a.x + a.y) + (a.z + a.w);
    }

    // y: reduce from smem, keep in registers for the scaled store.
    mbar_wait(mby, 0);

    const float4* sy4 = reinterpret_cast<const float4*>(sy);
    float4 yv[ITERS];
#pragma unroll
    for (int i = 0; i < ITERS; i++) {
        yv[i] = sy4[i * NTHREADS + tid];
        t += (yv[i].x + yv[i].y) + (yv[i].z + yv[i].w);
    }

    // One-barrier block reduction: warp partials -> smem, each thread sums 8.
#pragma unroll
    for (int o = 16; o > 0; o >>= 1)
        t += __shfl_xor_sync(0xffffffffu, t, o);
    if ((tid & 31) == 0)
        warpsum[wid] = t;
    __syncthreads();

    float s = 0.0f;
#pragma unroll
    for (int w = 0; w < NWARPS; w++)
        s += warpsum[w];
    const float sc = s * (1.0f / (float)L_LEN);

    // Streaming (evict-first) stores — measured-optimal policy.
    float4* orow = reinterpret_cast<float4*>(out + row_base);
#pragma unroll
    for (int i = 0; i < ITERS; i++) {
        float4 v = yv[i];
        v.x *= sc; v.y *= sc; v.z *= sc; v.w *= sc;
        __stcs(&orow[i * NTHREADS + tid], v);
    }
}

extern "C" void kernel_launch(void* const* d_in, const int* in_sizes, int n_in,
                              void* d_out, int out_size)
{
    const float* x = (const float*)d_in[0];
    const float* y = (const float*)d_in[1];
    float* out = (float*)d_out;

    const int rows = in_sizes[0] / L_LEN;   // 2304
    spo2_asym_kernel<<<rows, NTHREADS>>>(x, y, out);
}